// round 2
// baseline (speedup 1.0000x reference)
#include <cuda_runtime.h>
#include <stdint.h>

#define N_NODES 100000
#define BATCH   50000
#define K       10
#define DIM     128
#define SCALE   2048.0f

// int16 feature table scratch: 100000*128*2 = 25.6 MB (static device global — allowed)
__device__ short g_feat16[N_NODES * DIM];

// ---------------------------------------------------------------------------
// Pass 1: convert fp32 features -> int16 fixed point (scale 2048, range ±16).
// Each thread converts 4 floats (one float4) and stores 8 bytes (uint2).
// ---------------------------------------------------------------------------
__global__ __launch_bounds__(256) void convert_kernel(const float4* __restrict__ feat)
{
    const int i = blockIdx.x * blockDim.x + threadIdx.x;   // one float4 each
    const int n4 = N_NODES * DIM / 4;                      // 3.2M
    if (i >= n4) return;

    float4 a = feat[i];
    int s0 = __float2int_rn(a.x * SCALE);
    int s1 = __float2int_rn(a.y * SCALE);
    int s2 = __float2int_rn(a.z * SCALE);
    int s3 = __float2int_rn(a.w * SCALE);

    uint2 packed;
    packed.x = ((unsigned)s0 & 0xFFFFu) | ((unsigned)s1 << 16);
    packed.y = ((unsigned)s2 & 0xFFFFu) | ((unsigned)s3 << 16);
    reinterpret_cast<uint2*>(g_feat16)[i] = packed;
}

// ---------------------------------------------------------------------------
// Pass 2: gather-mean. One warp per output row. Each lane owns 4 output
// columns: loads 8 bytes (4 int16) per gathered row (uint2, 2-line wavefront),
// accumulates exactly in int32, converts once at the end.
// ---------------------------------------------------------------------------
__global__ __launch_bounds__(256) void gather_kernel(
    const int* __restrict__ nodes,
    const int* __restrict__ neighbours,
    float4* __restrict__ out)
{
    const int warp = (blockIdx.x * blockDim.x + threadIdx.x) >> 5;
    const int lane = threadIdx.x & 31;
    if (warp >= BATCH) return;

    int idx[K + 1];
    idx[0] = nodes[warp];
#pragma unroll
    for (int k = 0; k < K; k++) idx[k + 1] = neighbours[warp * K + k];

    const uint2* __restrict__ tab = reinterpret_cast<const uint2*>(g_feat16);

    // Front-batch all 11 gathered 8B loads (MLP=11).
    uint2 v[K + 1];
#pragma unroll
    for (int k = 0; k < K + 1; k++) {
        v[k] = __ldg(&tab[(long long)idx[k] * 32 + lane]);
    }

    int a0 = 0, a1 = 0, a2 = 0, a3 = 0;
#pragma unroll
    for (int k = 0; k < K + 1; k++) {
        a0 += (int)(short)(v[k].x & 0xFFFFu);
        a1 += ((int)v[k].x) >> 16;
        a2 += (int)(short)(v[k].y & 0xFFFFu);
        a3 += ((int)v[k].y) >> 16;
    }

    const float s = 1.0f / (SCALE * (float)(K + 1));
    float4 o;
    o.x = (float)a0 * s;
    o.y = (float)a1 * s;
    o.z = (float)a2 * s;
    o.w = (float)a3 * s;
    out[(long long)warp * 32 + lane] = o;
}

extern "C" void kernel_launch(void* const* d_in, const int* in_sizes, int n_in,
                              void* d_out, int out_size)
{
    const int*    nodes      = (const int*)d_in[0];
    const int*    neighbours = (const int*)d_in[1];
    const float4* features   = (const float4*)d_in[2];
    float4*       out        = (float4*)d_out;

    const int n4 = N_NODES * DIM / 4;
    convert_kernel<<<(n4 + 255) / 256, 256>>>(features);

    const int warps_per_block = 256 / 32;
    const int blocks = (BATCH + warps_per_block - 1) / warps_per_block;
    gather_kernel<<<blocks, 256>>>(nodes, neighbours, out);
}

// round 4
// speedup vs baseline: 1.1815x; 1.1815x over previous
#include <cuda_runtime.h>
#include <cuda_fp16.h>
#include <stdint.h>

#define N_NODES 100000
#define BATCH   50000
#define K       10
#define DIM     128

// fp16 feature table scratch: 100000*128*2 = 25.6 MB
__device__ __half g_tab16[N_NODES * DIM];

// ---------------------------------------------------------------------------
// Pass 1: convert fp32 features -> fp16 table.
// Each thread converts 8 floats (2 x float4 load) and stores one uint4 (16B).
// ---------------------------------------------------------------------------
__global__ __launch_bounds__(256) void convert_kernel(const float4* __restrict__ feat)
{
    const int i = blockIdx.x * blockDim.x + threadIdx.x;   // one uint4 (8 halfs)
    const int n8 = N_NODES * DIM / 8;                      // 1.6M
    if (i >= n8) return;

    float4 a = __ldg(&feat[i * 2 + 0]);
    float4 b = __ldg(&feat[i * 2 + 1]);

    __half2 h0 = __float22half2_rn(make_float2(a.x, a.y));
    __half2 h1 = __float22half2_rn(make_float2(a.z, a.w));
    __half2 h2 = __float22half2_rn(make_float2(b.x, b.y));
    __half2 h3 = __float22half2_rn(make_float2(b.z, b.w));

    uint4 packed;
    packed.x = *reinterpret_cast<unsigned*>(&h0);
    packed.y = *reinterpret_cast<unsigned*>(&h1);
    packed.z = *reinterpret_cast<unsigned*>(&h2);
    packed.w = *reinterpret_cast<unsigned*>(&h3);
    reinterpret_cast<uint4*>(g_tab16)[i] = packed;
}

// ---------------------------------------------------------------------------
// Pass 2: gather-mean. One warp per output row. fp16 row = 256B; each lane
// loads one uint2 (4 halfs = 2 x half2). Inner loop is pure HADD2.
// ---------------------------------------------------------------------------
__global__ __launch_bounds__(256) void gather_kernel(
    const int* __restrict__ nodes,
    const int* __restrict__ neighbours,
    float4* __restrict__ out)
{
    const int warp = (blockIdx.x * blockDim.x + threadIdx.x) >> 5;
    const int lane = threadIdx.x & 31;
    if (warp >= BATCH) return;

    int idx[K + 1];
    idx[0] = nodes[warp];
#pragma unroll
    for (int k = 0; k < K; k++) idx[k + 1] = neighbours[warp * K + k];

    const uint2* __restrict__ tab = reinterpret_cast<const uint2*>(g_tab16);

    // Front-batch all 11 gathered 8B loads (MLP=11, two 128B lines per warp).
    uint2 v[K + 1];
#pragma unroll
    for (int k = 0; k < K + 1; k++) {
        v[k] = __ldg(&tab[idx[k] * (DIM / 4) + lane]);
    }

    __half2 acc01 = *reinterpret_cast<__half2*>(&v[0].x);
    __half2 acc23 = *reinterpret_cast<__half2*>(&v[0].y);
#pragma unroll
    for (int k = 1; k < K + 1; k++) {
        acc01 = __hadd2(acc01, *reinterpret_cast<__half2*>(&v[k].x));
        acc23 = __hadd2(acc23, *reinterpret_cast<__half2*>(&v[k].y));
    }

    const float s = 1.0f / (float)(K + 1);
    float2 f01 = __half22float2(acc01);
    float2 f23 = __half22float2(acc23);

    float4 o;
    o.x = f01.x * s;
    o.y = f01.y * s;
    o.z = f23.x * s;
    o.w = f23.y * s;
    out[warp * (DIM / 4) + lane] = o;
}

extern "C" void kernel_launch(void* const* d_in, const int* in_sizes, int n_in,
                              void* d_out, int out_size)
{
    const int*    nodes      = (const int*)d_in[0];
    const int*    neighbours = (const int*)d_in[1];
    const float4* features   = (const float4*)d_in[2];
    float4*       out        = (float4*)d_out;

    const int n8 = N_NODES * DIM / 8;
    convert_kernel<<<(n8 + 255) / 256, 256>>>(features);

    const int warps_per_block = 256 / 32;
    const int blocks = (BATCH + warps_per_block - 1) / warps_per_block;
    gather_kernel<<<blocks, 256>>>(nodes, neighbours, out);
}

// round 5
// speedup vs baseline: 1.2766x; 1.0805x over previous
#include <cuda_runtime.h>
#include <cuda_fp16.h>
#include <stdint.h>

#define N_NODES 100000
#define BATCH   50000
#define K       10
#define DIM     128

// fp16 feature table scratch: 100000*128*2 = 25.6 MB (the ONLY data we want
// resident in L2 — everything else is streamed around it).
__device__ __half g_tab16[N_NODES * DIM];

// ---------------------------------------------------------------------------
// Pass 1: convert fp32 features -> fp16 table.
// Feature reads use __ldcs (evict-first streaming): they are touched exactly
// once per launch and must not evict the fp16 table from L2.
// ---------------------------------------------------------------------------
__global__ __launch_bounds__(256) void convert_kernel(const float4* __restrict__ feat)
{
    const int i = blockIdx.x * blockDim.x + threadIdx.x;   // one uint4 (8 halfs)
    const int n8 = N_NODES * DIM / 8;                      // 1.6M
    if (i >= n8) return;

    float4 a = __ldcs(&feat[i * 2 + 0]);
    float4 b = __ldcs(&feat[i * 2 + 1]);

    __half2 h0 = __float22half2_rn(make_float2(a.x, a.y));
    __half2 h1 = __float22half2_rn(make_float2(a.z, a.w));
    __half2 h2 = __float22half2_rn(make_float2(b.x, b.y));
    __half2 h3 = __float22half2_rn(make_float2(b.z, b.w));

    uint4 packed;
    packed.x = *reinterpret_cast<unsigned*>(&h0);
    packed.y = *reinterpret_cast<unsigned*>(&h1);
    packed.z = *reinterpret_cast<unsigned*>(&h2);
    packed.w = *reinterpret_cast<unsigned*>(&h3);
    reinterpret_cast<uint4*>(g_tab16)[i] = packed;          // default policy: keep in L2
}

// ---------------------------------------------------------------------------
// Pass 2: gather-mean. One warp per output row; lane owns 4 columns (uint2,
// 8B per gathered row). Inner loop is pure HADD2. Output is written with
// __stcs (streaming) — write-once data must not evict the table.
// ---------------------------------------------------------------------------
__global__ __launch_bounds__(256) void gather_kernel(
    const int* __restrict__ nodes,
    const int* __restrict__ neighbours,
    float4* __restrict__ out)
{
    const int warp = (blockIdx.x * blockDim.x + threadIdx.x) >> 5;
    const int lane = threadIdx.x & 31;
    if (warp >= BATCH) return;

    int idx[K + 1];
    idx[0] = nodes[warp];
#pragma unroll
    for (int k = 0; k < K; k++) idx[k + 1] = neighbours[warp * K + k];

    const uint2* __restrict__ tab = reinterpret_cast<const uint2*>(g_tab16);

    // Front-batch all 11 gathered 8B loads (MLP=11, 2 x 128B lines per warp).
    uint2 v[K + 1];
#pragma unroll
    for (int k = 0; k < K + 1; k++) {
        v[k] = __ldg(&tab[idx[k] * (DIM / 4) + lane]);
    }

    __half2 acc01 = *reinterpret_cast<__half2*>(&v[0].x);
    __half2 acc23 = *reinterpret_cast<__half2*>(&v[0].y);
#pragma unroll
    for (int k = 1; k < K + 1; k++) {
        acc01 = __hadd2(acc01, *reinterpret_cast<__half2*>(&v[k].x));
        acc23 = __hadd2(acc23, *reinterpret_cast<__half2*>(&v[k].y));
    }

    const float s = 1.0f / (float)(K + 1);
    float2 f01 = __half22float2(acc01);
    float2 f23 = __half22float2(acc23);

    float4 o;
    o.x = f01.x * s;
    o.y = f01.y * s;
    o.z = f23.x * s;
    o.w = f23.y * s;
    __stcs(&out[warp * (DIM / 4) + lane], o);   // streaming store: don't pollute L2
}

extern "C" void kernel_launch(void* const* d_in, const int* in_sizes, int n_in,
                              void* d_out, int out_size)
{
    const int*    nodes      = (const int*)d_in[0];
    const int*    neighbours = (const int*)d_in[1];
    const float4* features   = (const float4*)d_in[2];
    float4*       out        = (float4*)d_out;

    const int n8 = N_NODES * DIM / 8;
    convert_kernel<<<(n8 + 255) / 256, 256>>>(features);

    const int warps_per_block = 256 / 32;
    const int blocks = (BATCH + warps_per_block - 1) / warps_per_block;
    gather_kernel<<<blocks, 256>>>(nodes, neighbours, out);
}